// round 1
// baseline (speedup 1.0000x reference)
#include <cuda_runtime.h>
#include <math.h>

#define Bb    8
#define Cc    256
#define HW    4096
#define PER_B (Cc * HW)          // 1048576 = 2^20
#define EPSF  1e-12f

// ---------------- device scratch (allocation-free contract) ----------------
__device__ float g_Q[7][Bb * PER_B];   // unnormalized Krylov vectors, slots 1..7 (slot 0 = input v)
__device__ float g_R[Bb * PER_B];      // replicator output
__device__ float g_w[Bb * PER_B];      // GEMM output
__device__ float g_dpart[8][Bb][512];  // dot partials [j][b][blk]
__device__ float g_npart[Bb][512];     // norm partials
__device__ float g_H[Bb][8][8];        // H[b][row j][col k] (zero-init)
__device__ float g_inv[8][Bb];         // 1/norm of vector j (j=0: 1/vnorm; else 1/(h+eps))
__device__ float g_hcoef[8][Bb];       // h_j * inv_j for update pass
__device__ float g_vnorm[Bb];
__device__ float g_cf[Bb][8];          // final combine coefficients

// ---------------- helpers ----------------
__device__ __forceinline__ float blockReduce256(float val) {
    __shared__ float sh[256];
    int t = threadIdx.x;
    sh[t] = val; __syncthreads();
    #pragma unroll
    for (int s = 128; s > 0; s >>= 1) {
        if (t < s) sh[t] += sh[t + s];
        __syncthreads();
    }
    float r = sh[0];
    __syncthreads();
    return r;
}

// ---------------- ||v||^2 partials ----------------
__global__ void __launch_bounds__(256) k_selfdot(const float* __restrict__ v) {
    int b = blockIdx.y, blk = blockIdx.x, t = threadIdx.x;
    size_t base = (size_t)b * PER_B + (size_t)blk * 2048 + t;
    float acc = 0.f;
    #pragma unroll
    for (int e = 0; e < 8; e++) { float x = v[base + e * 256]; acc += x * x; }
    float r = blockReduce256(acc);
    if (t == 0) g_npart[b][blk] = r;
}

__global__ void k_vnorm_fin() {
    int b = blockIdx.x, t = threadIdx.x;
    float s = g_npart[b][t] + g_npart[b][t + 256];
    float r = blockReduce256(s);
    if (t == 0) { float vn = sqrtf(r); g_vnorm[b] = vn; g_inv[0][b] = 1.f / vn; }
}

// ---------------- replicator: R = inv * s0 * (q - sum_c(s0*q)) ----------------
// block: (p-tile of 32) x batch; thread = (p lane 0..31, c-group 0..7), 32 c per thread in regs
__global__ void __launch_bounds__(256) k_replicator(const float* __restrict__ s0,
                                                    const float* __restrict__ v, int k) {
    const float* __restrict__ qu = (k == 0) ? v : g_Q[k - 1];
    int b  = blockIdx.y;
    int p  = blockIdx.x * 32 + (threadIdx.x & 31);
    int cg = threadIdx.x >> 5;
    float inv = g_inv[k][b];
    size_t base = (size_t)b * PER_B + p;

    float sv[32], qv[32];
    float part = 0.f;
    #pragma unroll
    for (int i = 0; i < 32; i++) {
        size_t off = base + (size_t)(cg * 32 + i) * HW;
        sv[i] = s0[off]; qv[i] = qu[off];
        part += sv[i] * qv[i];
    }
    __shared__ float red[8][32];
    __shared__ float Ssh[32];
    red[cg][threadIdx.x & 31] = part;
    __syncthreads();
    if (cg == 0) {
        float s = 0.f;
        #pragma unroll
        for (int g = 0; g < 8; g++) s += red[g][threadIdx.x];
        Ssh[threadIdx.x] = s;
    }
    __syncthreads();
    float S = Ssh[threadIdx.x & 31];
    #pragma unroll
    for (int i = 0; i < 32; i++) {
        size_t off = base + (size_t)(cg * 32 + i) * HW;
        g_R[off] = inv * sv[i] * (qv[i] - S);
    }
}

// ---------------- GEMM: w[b,o,p] = sum_c W[o,c] * R[b,c,p] ----------------
// BM=256 (full M, R read once), BN=64, BK=16; 256 threads; 8x8 per thread
__global__ void __launch_bounds__(256, 2) k_gemm(const float* __restrict__ Wm) {
    const int b  = blockIdx.y;
    const int p0 = blockIdx.x * 64;
    const int tid = threadIdx.x;
    const int tm = tid >> 3;  // 0..31 -> m = tm*8..
    const int tn = tid & 7;   // 0..7  -> n = tn*8..

    __shared__ float As[16][256];
    __shared__ float Bs[16][64];

    const float* __restrict__ Rb = g_R + (size_t)b * PER_B + p0;
    float acc[8][8];
    #pragma unroll
    for (int i = 0; i < 8; i++)
        #pragma unroll
        for (int j = 0; j < 8; j++) acc[i][j] = 0.f;

    for (int kc = 0; kc < 256; kc += 16) {
        // A tile: W[0..255][kc..kc+15] -> As[k][m] (transposed)
        #pragma unroll
        for (int i = 0; i < 4; i++) {
            int f4  = tid + 256 * i;
            int row = f4 >> 2;
            int c4  = (f4 & 3) * 4;
            float4 a = *(const float4*)(Wm + row * 256 + kc + c4);
            As[c4 + 0][row] = a.x; As[c4 + 1][row] = a.y;
            As[c4 + 2][row] = a.z; As[c4 + 3][row] = a.w;
        }
        // B tile: R[kc..kc+15][p0..p0+63]
        {
            int row = tid >> 4;
            int c4  = (tid & 15) * 4;
            float4 bv = *(const float4*)(Rb + (size_t)(kc + row) * HW + c4);
            *(float4*)&Bs[row][c4] = bv;
        }
        __syncthreads();
        #pragma unroll
        for (int kk = 0; kk < 16; kk++) {
            float av[8], bv[8];
            #pragma unroll
            for (int i = 0; i < 8; i++) av[i] = As[kk][tm * 8 + i];
            #pragma unroll
            for (int j = 0; j < 8; j++) bv[j] = Bs[kk][tn * 8 + j];
            #pragma unroll
            for (int i = 0; i < 8; i++)
                #pragma unroll
                for (int j = 0; j < 8; j++) acc[i][j] += av[i] * bv[j];
        }
        __syncthreads();
    }
    float* ob = g_w + (size_t)b * PER_B + p0;
    #pragma unroll
    for (int i = 0; i < 8; i++) {
        int m = tm * 8 + i;
        #pragma unroll
        for (int j = 0; j < 8; j += 4) {
            float4 vv = make_float4(acc[i][j], acc[i][j+1], acc[i][j+2], acc[i][j+3]);
            *(float4*)(ob + (size_t)m * HW + tn * 8 + j) = vv;
        }
    }
}

// ---------------- dots: partials of <Q_j, w> for j=0..KK (classical GS) ----------------
template <int KK>
__global__ void __launch_bounds__(256) k_dots(const float* __restrict__ v) {
    int b = blockIdx.y, blk = blockIdx.x, t = threadIdx.x;
    size_t base = (size_t)b * PER_B + (size_t)blk * 2048 + t;
    const float* qs[KK + 1];
    float acc[KK + 1];
    #pragma unroll
    for (int j = 0; j <= KK; j++) { qs[j] = (j == 0) ? v : g_Q[j - 1]; acc[j] = 0.f; }
    #pragma unroll
    for (int e = 0; e < 8; e++) {
        size_t idx = base + e * 256;
        float wv = g_w[idx];
        #pragma unroll
        for (int j = 0; j <= KK; j++) acc[j] += qs[j][idx] * wv;
    }
    __shared__ float sh[256];
    #pragma unroll
    for (int j = 0; j <= KK; j++) {
        sh[t] = acc[j]; __syncthreads();
        #pragma unroll
        for (int s = 128; s > 0; s >>= 1) { if (t < s) sh[t] += sh[t + s]; __syncthreads(); }
        if (t == 0) g_dpart[j][b][blk] = sh[0];
        __syncthreads();
    }
}

__global__ void k_dots_fin(int k) {
    int j = blockIdx.x, b = blockIdx.y, t = threadIdx.x;
    float s = g_dpart[j][b][t] + g_dpart[j][b][t + 256];
    float r = blockReduce256(s);
    if (t == 0) {
        float h = r * g_inv[j][b];     // dot against normalized Q_j
        g_H[b][j][k]  = h;
        g_hcoef[j][b] = h * g_inv[j][b];
    }
}

// ---------------- update: Qu[k+1] = w - sum_j (h_j*inv_j)*Qu_j ; norm partials ----------------
template <int KK>
__global__ void __launch_bounds__(256) k_update(const float* __restrict__ v) {
    int b = blockIdx.y, blk = blockIdx.x, t = threadIdx.x;
    size_t base = (size_t)b * PER_B + (size_t)blk * 2048 + t;
    const float* qs[KK + 1];
    float cf[KK + 1];
    #pragma unroll
    for (int j = 0; j <= KK; j++) { qs[j] = (j == 0) ? v : g_Q[j - 1]; cf[j] = g_hcoef[j][b]; }
    float* __restrict__ qn = g_Q[KK];   // slot KK+1
    float nacc = 0.f;
    #pragma unroll
    for (int e = 0; e < 8; e++) {
        size_t idx = base + e * 256;
        float x = g_w[idx];
        #pragma unroll
        for (int j = 0; j <= KK; j++) x -= cf[j] * qs[j][idx];
        qn[idx] = x;
        nacc += x * x;
    }
    float r = blockReduce256(nacc);
    if (t == 0) g_npart[b][blk] = r;
}

__global__ void k_norm_fin(int k) {
    int b = blockIdx.x, t = threadIdx.x;
    float s = g_npart[b][t] + g_npart[b][t + 256];
    float r = blockReduce256(s);
    if (t == 0) {
        float hn = sqrtf(r);
        g_H[b][k + 1][k] = hn;
        g_inv[k + 1][b]  = 1.f / (hn + EPSF);
    }
}

// ---------------- expm of 9x9 extended matrix (scaling-squaring + Taylor, fp64) ----------------
__global__ void k_expm() {
    const int b = blockIdx.x;
    const int t = threadIdx.x;            // 128 threads, 81 active
    __shared__ double A[81], M[81], P[81], Pn[81];
    __shared__ int ssc;

    if (t < 81) {
        int i = t / 9, j = t % 9;
        double e = 0.0;
        if (i < 8 && j < 8) e = (double)g_H[b][i][j];   // T_END = 1.0
        if (i == 0 && j == 8) e = 1.0;                   // ext[0, m] = T_END
        A[t] = e;
    }
    __syncthreads();
    if (t == 0) {
        double nrm = 0.0;
        for (int i = 0; i < 9; i++) {
            double rs = 0.0;
            for (int j = 0; j < 9; j++) rs += fabs(A[i * 9 + j]);
            if (rs > nrm) nrm = rs;
        }
        int s = 0;
        while (nrm > 0.5 && s < 60) { nrm *= 0.5; s++; }
        ssc = s;
    }
    __syncthreads();
    const int s = ssc;
    if (t < 81) {
        A[t] = ldexp(A[t], -s);
        M[t] = ((t % 10 == 0) ? 1.0 : 0.0) + A[t];   // I + A
        P[t] = A[t];
    }
    __syncthreads();
    for (int it = 2; it <= 22; it++) {
        if (t < 81) {
            int i = t / 9, j = t % 9;
            double acc = 0.0;
            #pragma unroll
            for (int kk = 0; kk < 9; kk++) acc += P[i * 9 + kk] * A[kk * 9 + j];
            Pn[t] = acc / (double)it;
        }
        __syncthreads();
        if (t < 81) { P[t] = Pn[t]; M[t] += P[t]; }
        __syncthreads();
    }
    for (int q = 0; q < s; q++) {
        if (t < 81) {
            int i = t / 9, j = t % 9;
            double acc = 0.0;
            #pragma unroll
            for (int kk = 0; kk < 9; kk++) acc += M[i * 9 + kk] * M[kk * 9 + j];
            Pn[t] = acc;
        }
        __syncthreads();
        if (t < 81) M[t] = Pn[t];
        __syncthreads();
    }
    if (t < 8) {
        double coord = M[t * 9 + 8];
        g_cf[b][t] = (float)(coord * (double)g_vnorm[b] * (double)g_inv[t][b]);
    }
}

// ---------------- final combine: out = vnorm * sum_j coords_j * inv_j * Qu_j ----------------
__global__ void __launch_bounds__(256) k_combine(const float* __restrict__ v,
                                                 float* __restrict__ out) {
    int b = blockIdx.y, blk = blockIdx.x, t = threadIdx.x;
    size_t base = (size_t)b * PER_B + (size_t)blk * 2048 + t;
    const float* qs[8];
    float cf[8];
    #pragma unroll
    for (int j = 0; j < 8; j++) { qs[j] = (j == 0) ? v : g_Q[j - 1]; cf[j] = g_cf[b][j]; }
    #pragma unroll
    for (int e = 0; e < 8; e++) {
        size_t idx = base + e * 256;
        float x = 0.f;
        #pragma unroll
        for (int j = 0; j < 8; j++) x += cf[j] * qs[j][idx];
        out[idx] = x;
    }
}

// ---------------- driver ----------------
extern "C" void kernel_launch(void* const* d_in, const int* in_sizes, int n_in,
                              void* d_out, int out_size) {
    const float* s0 = (const float*)d_in[0];
    const float* v  = (const float*)d_in[1];
    const float* Wm = (const float*)d_in[2];
    float* out = (float*)d_out;

    dim3 gEl(512, Bb);    // elementwise / reduction grids: 512 blocks/batch * 2048 elems
    dim3 gRep(HW / 32, Bb);
    dim3 gGemm(HW / 64, Bb);

    k_selfdot<<<gEl, 256>>>(v);
    k_vnorm_fin<<<Bb, 256>>>();

    for (int k = 0; k < 8; k++) {
        k_replicator<<<gRep, 256>>>(s0, v, k);
        k_gemm<<<gGemm, 256>>>(Wm);

        switch (k) {
            case 0: k_dots<0><<<gEl, 256>>>(v); break;
            case 1: k_dots<1><<<gEl, 256>>>(v); break;
            case 2: k_dots<2><<<gEl, 256>>>(v); break;
            case 3: k_dots<3><<<gEl, 256>>>(v); break;
            case 4: k_dots<4><<<gEl, 256>>>(v); break;
            case 5: k_dots<5><<<gEl, 256>>>(v); break;
            case 6: k_dots<6><<<gEl, 256>>>(v); break;
            case 7: k_dots<7><<<gEl, 256>>>(v); break;
        }
        k_dots_fin<<<dim3(k + 1, Bb), 256>>>(k);

        if (k < 7) {
            switch (k) {
                case 0: k_update<0><<<gEl, 256>>>(v); break;
                case 1: k_update<1><<<gEl, 256>>>(v); break;
                case 2: k_update<2><<<gEl, 256>>>(v); break;
                case 3: k_update<3><<<gEl, 256>>>(v); break;
                case 4: k_update<4><<<gEl, 256>>>(v); break;
                case 5: k_update<5><<<gEl, 256>>>(v); break;
                case 6: k_update<6><<<gEl, 256>>>(v); break;
            }
            k_norm_fin<<<Bb, 256>>>(k);
        }
    }

    k_expm<<<Bb, 128>>>();
    k_combine<<<gEl, 256>>>(v, out);
}

// round 3
// speedup vs baseline: 1.5136x; 1.5136x over previous
#include <cuda_runtime.h>
#include <cuda_bf16.h>
#include <math.h>
#include <stdint.h>

#define Bb    8
#define Cc    256
#define HW    4096
#define PER_B (Cc * HW)          // 2^20
#define EPSF  1e-12f

// ---------------- device scratch ----------------
__device__ float g_Q[7][Bb * PER_B];   // unnormalized Krylov vectors, slots 1..7 (slot 0 = input v)
__device__ float g_w[Bb * PER_B];      // GEMM output
__device__ __nv_bfloat16 g_Rhi[Bb * PER_B];  // replicator output, transposed [b][p][c], bf16 hi
__device__ __nv_bfloat16 g_Rlo[Bb * PER_B];  // bf16 lo residual
__device__ __nv_bfloat16 g_Whi[Cc * Cc];
__device__ __nv_bfloat16 g_Wlo[Cc * Cc];
__device__ float g_dpart[8][Bb][512];
__device__ float g_npart[Bb][512];
__device__ float g_H[Bb][8][8];
__device__ float g_inv[8][Bb];
__device__ float g_hcoef[8][Bb];
__device__ float g_vnorm[Bb];
__device__ float g_cf[Bb][8];

// ---------------- helpers ----------------
__device__ __forceinline__ float blockReduce256(float val) {
    __shared__ float sh[256];
    int t = threadIdx.x;
    sh[t] = val; __syncthreads();
    #pragma unroll
    for (int s = 128; s > 0; s >>= 1) {
        if (t < s) sh[t] += sh[t + s];
        __syncthreads();
    }
    float r = sh[0];
    __syncthreads();
    return r;
}

// ---------------- ||v||^2 ----------------
__global__ void __launch_bounds__(256) k_selfdot(const float* __restrict__ v) {
    int b = blockIdx.y, blk = blockIdx.x, t = threadIdx.x;
    size_t base = (size_t)b * PER_B + (size_t)blk * 2048 + t;
    float acc = 0.f;
    #pragma unroll
    for (int e = 0; e < 8; e++) { float x = v[base + e * 256]; acc += x * x; }
    float r = blockReduce256(acc);
    if (t == 0) g_npart[b][blk] = r;
}

__global__ void k_vnorm_fin() {
    int b = blockIdx.x, t = threadIdx.x;
    float s = g_npart[b][t] + g_npart[b][t + 256];
    float r = blockReduce256(s);
    if (t == 0) { float vn = sqrtf(r); g_vnorm[b] = vn; g_inv[0][b] = 1.f / vn; }
}

// ---------------- W split to bf16 hi/lo ----------------
__global__ void __launch_bounds__(256) k_splitW(const float* __restrict__ Wm) {
    int i = blockIdx.x * 256 + threadIdx.x;
    float x = Wm[i];
    __nv_bfloat16 h = __float2bfloat16(x);
    g_Whi[i] = h;
    g_Wlo[i] = __float2bfloat16(x - __bfloat162float(h));
}

// ---------------- replicator: R_t[b][p][c] = bf16split( inv * s0 * (q - sum_c(s0*q)) ) ----------------
__global__ void __launch_bounds__(256) k_replicator(const float* __restrict__ s0,
                                                    const float* __restrict__ v, int k) {
    const float* __restrict__ qu = (k == 0) ? v : g_Q[k - 1];
    int b  = blockIdx.y;
    int p  = blockIdx.x * 32 + (threadIdx.x & 31);
    int cg = threadIdx.x >> 5;
    float inv = g_inv[k][b];
    size_t base = (size_t)b * PER_B + p;

    float sv[32], qv[32];
    float part = 0.f;
    #pragma unroll
    for (int i = 0; i < 32; i++) {
        size_t off = base + (size_t)(cg * 32 + i) * HW;
        sv[i] = s0[off]; qv[i] = qu[off];
        part += sv[i] * qv[i];
    }
    __shared__ float red[8][32];
    __shared__ float Ssh[32];
    red[cg][threadIdx.x & 31] = part;
    __syncthreads();
    if (cg == 0) {
        float s = 0.f;
        #pragma unroll
        for (int g = 0; g < 8; g++) s += red[g][threadIdx.x];
        Ssh[threadIdx.x] = s;
    }
    __syncthreads();
    float S = Ssh[threadIdx.x & 31];

    uint32_t phi[16], plo[16];
    #pragma unroll
    for (int i = 0; i < 16; i++) {
        float x0 = inv * sv[2*i]     * (qv[2*i]     - S);
        float x1 = inv * sv[2*i + 1] * (qv[2*i + 1] - S);
        __nv_bfloat16 h0 = __float2bfloat16(x0);
        __nv_bfloat16 h1 = __float2bfloat16(x1);
        __nv_bfloat16 l0 = __float2bfloat16(x0 - __bfloat162float(h0));
        __nv_bfloat16 l1 = __float2bfloat16(x1 - __bfloat162float(h1));
        phi[i] = (uint32_t)__bfloat16_as_ushort(h0) | ((uint32_t)__bfloat16_as_ushort(h1) << 16);
        plo[i] = (uint32_t)__bfloat16_as_ushort(l0) | ((uint32_t)__bfloat16_as_ushort(l1) << 16);
    }
    size_t ob = ((size_t)b * HW + p) * 256 + cg * 32;   // transposed layout, c contiguous
    uint4* dh = (uint4*)(g_Rhi + ob);
    uint4* dl = (uint4*)(g_Rlo + ob);
    #pragma unroll
    for (int i = 0; i < 4; i++) {
        dh[i] = make_uint4(phi[4*i], phi[4*i+1], phi[4*i+2], phi[4*i+3]);
        dl[i] = make_uint4(plo[4*i], plo[4*i+1], plo[4*i+2], plo[4*i+3]);
    }
}

// ---------------- tensor-core GEMM via mma.sync (bf16, 3-term split) ----------------
// w[b,o,p] = sum_c W[o,c] * R[b,c,p];  Whi*Rhi + Whi*Rlo + Wlo*Rhi, fp32 accum.
// CTA: 128(o) x 128(p), K chunks of 64. 8 warps (2m x 4n), warp tile 64x32.
static __device__ __forceinline__ void ldtile(char* tbp, uint32_t off,
                                              const __nv_bfloat16* src, int kc, int tid) {
    #pragma unroll
    for (int i = 0; i < 4; i++) {
        int x = tid + (i << 8);          // 0..1023 16B units
        int row = x >> 3;                // 128B rows
        int cb  = (x & 7) << 4;          // byte within row
        uint4 v = *(const uint4*)((const char*)(src + (size_t)row * 256 + kc) + cb);
        uint32_t bo = (uint32_t)(row * 128 + (cb ^ ((row & 7) << 4)));   // SW128 swizzle
        *(uint4*)(tbp + off + bo) = v;
    }
}

static __device__ __forceinline__ void mma_bf16(float* c, const uint32_t* a, const uint32_t* b) {
    asm volatile("mma.sync.aligned.m16n8k16.row.col.f32.bf16.bf16.f32 "
        "{%0,%1,%2,%3}, {%4,%5,%6,%7}, {%8,%9}, {%0,%1,%2,%3};"
        : "+f"(c[0]), "+f"(c[1]), "+f"(c[2]), "+f"(c[3])
        : "r"(a[0]), "r"(a[1]), "r"(a[2]), "r"(a[3]), "r"(b[0]), "r"(b[1]));
}

__global__ void __launch_bounds__(256, 2) k_gemm_mma() {
    extern __shared__ __align__(16) char smem[];
    const int tid  = threadIdx.x;
    const int wid  = tid >> 5;
    const int lane = tid & 31;
    const int g    = lane >> 2;       // 0..7
    const int q    = lane & 3;        // 0..3
    const int wm   = wid >> 2;        // 0..1 -> m warp tile
    const int wn   = wid & 3;         // 0..3 -> n warp tile
    const int p0   = blockIdx.x * 128;
    const int mt   = blockIdx.y;
    const int b    = blockIdx.z;

    const uint32_t OFF_AH = 0, OFF_AL = 16384, OFF_BH = 32768, OFF_BL = 49152;
    const uint32_t swz = (uint32_t)(g << 4);   // per-thread SW128 xor (row&7 == g for all frag rows)

    const __nv_bfloat16* Ahi = g_Whi + (size_t)mt * 128 * 256;
    const __nv_bfloat16* Alo = g_Wlo + (size_t)mt * 128 * 256;
    const __nv_bfloat16* Bhi = g_Rhi + ((size_t)b * HW + p0) * 256;
    const __nv_bfloat16* Blo = g_Rlo + ((size_t)b * HW + p0) * 256;

    float acc[4][4][4];
    #pragma unroll
    for (int i = 0; i < 4; i++)
        #pragma unroll
        for (int j = 0; j < 4; j++)
            #pragma unroll
            for (int e = 0; e < 4; e++) acc[i][j][e] = 0.f;

    for (int kc = 0; kc < 256; kc += 64) {
        ldtile(smem, OFF_AH, Ahi, kc, tid);
        ldtile(smem, OFF_AL, Alo, kc, tid);
        ldtile(smem, OFF_BH, Bhi, kc, tid);
        ldtile(smem, OFF_BL, Blo, kc, tid);
        __syncthreads();

        #pragma unroll
        for (int kf = 0; kf < 4; kf++) {
            const uint32_t cb0 = (uint32_t)(kf * 32 + q * 4);
            uint32_t ah[4][4], al[4][4], bb[4][2];
            // A fragments (hi & lo): rows wm*64 + mf*16 + g (+8)
            #pragma unroll
            for (int mf = 0; mf < 4; mf++) {
                uint32_t r0 = (uint32_t)(wm * 64 + mf * 16 + g) * 128;
                uint32_t r1 = r0 + 8 * 128;
                uint32_t c0 = cb0 ^ swz, c1 = (cb0 + 16) ^ swz;
                ah[mf][0] = *(const uint32_t*)(smem + OFF_AH + r0 + c0);
                ah[mf][1] = *(const uint32_t*)(smem + OFF_AH + r1 + c0);
                ah[mf][2] = *(const uint32_t*)(smem + OFF_AH + r0 + c1);
                ah[mf][3] = *(const uint32_t*)(smem + OFF_AH + r1 + c1);
                al[mf][0] = *(const uint32_t*)(smem + OFF_AL + r0 + c0);
                al[mf][1] = *(const uint32_t*)(smem + OFF_AL + r1 + c0);
                al[mf][2] = *(const uint32_t*)(smem + OFF_AL + r0 + c1);
                al[mf][3] = *(const uint32_t*)(smem + OFF_AL + r1 + c1);
            }
            // B hi fragments: rows (n) = wn*32 + nf*8 + g
            #pragma unroll
            for (int nf = 0; nf < 4; nf++) {
                uint32_t nr = (uint32_t)(wn * 32 + nf * 8 + g) * 128;
                bb[nf][0] = *(const uint32_t*)(smem + OFF_BH + nr + (cb0 ^ swz));
                bb[nf][1] = *(const uint32_t*)(smem + OFF_BH + nr + ((cb0 + 16) ^ swz));
            }
            #pragma unroll
            for (int mf = 0; mf < 4; mf++)
                #pragma unroll
                for (int nf = 0; nf < 4; nf++) {
                    mma_bf16(acc[mf][nf], ah[mf], bb[nf]);   // Whi * Rhi
                    mma_bf16(acc[mf][nf], al[mf], bb[nf]);   // Wlo * Rhi
                }
            // B lo fragments (reuse regs)
            #pragma unroll
            for (int nf = 0; nf < 4; nf++) {
                uint32_t nr = (uint32_t)(wn * 32 + nf * 8 + g) * 128;
                bb[nf][0] = *(const uint32_t*)(smem + OFF_BL + nr + (cb0 ^ swz));
                bb[nf][1] = *(const uint32_t*)(smem + OFF_BL + nr + ((cb0 + 16) ^ swz));
            }
            #pragma unroll
            for (int mf = 0; mf < 4; mf++)
                #pragma unroll
                for (int nf = 0; nf < 4; nf++)
                    mma_bf16(acc[mf][nf], ah[mf], bb[nf]);   // Whi * Rlo
        }
        __syncthreads();
    }

    // epilogue: direct stores (each 4-lane group covers a full 32B sector)
    float* dst = g_w + (size_t)b * PER_B + (size_t)(mt * 128) * HW + p0;
    #pragma unroll
    for (int mf = 0; mf < 4; mf++) {
        int r0 = wm * 64 + mf * 16 + g;
        #pragma unroll
        for (int nf = 0; nf < 4; nf++) {
            int pp = wn * 32 + nf * 8 + q * 2;
            *(float2*)(dst + (size_t)r0 * HW + pp)       = make_float2(acc[mf][nf][0], acc[mf][nf][1]);
            *(float2*)(dst + (size_t)(r0 + 8) * HW + pp) = make_float2(acc[mf][nf][2], acc[mf][nf][3]);
        }
    }
}

// ---------------- dots: partials of <Q_j, w> ----------------
template <int KK>
__global__ void __launch_bounds__(256) k_dots(const float* __restrict__ v) {
    int b = blockIdx.y, blk = blockIdx.x, t = threadIdx.x;
    size_t base = (size_t)b * PER_B + (size_t)blk * 2048 + t;
    const float* qs[KK + 1];
    float acc[KK + 1];
    #pragma unroll
    for (int j = 0; j <= KK; j++) { qs[j] = (j == 0) ? v : g_Q[j - 1]; acc[j] = 0.f; }
    #pragma unroll
    for (int e = 0; e < 8; e++) {
        size_t idx = base + e * 256;
        float wv = g_w[idx];
        #pragma unroll
        for (int j = 0; j <= KK; j++) acc[j] += qs[j][idx] * wv;
    }
    __shared__ float sh[256];
    #pragma unroll
    for (int j = 0; j <= KK; j++) {
        sh[t] = acc[j]; __syncthreads();
        #pragma unroll
        for (int s = 128; s > 0; s >>= 1) { if (t < s) sh[t] += sh[t + s]; __syncthreads(); }
        if (t == 0) g_dpart[j][b][blk] = sh[0];
        __syncthreads();
    }
}

__global__ void k_dots_fin(int k) {
    int j = blockIdx.x, b = blockIdx.y, t = threadIdx.x;
    float s = g_dpart[j][b][t] + g_dpart[j][b][t + 256];
    float r = blockReduce256(s);
    if (t == 0) {
        float h = r * g_inv[j][b];
        g_H[b][j][k]  = h;
        g_hcoef[j][b] = h * g_inv[j][b];
    }
}

// ---------------- update + norm ----------------
template <int KK>
__global__ void __launch_bounds__(256) k_update(const float* __restrict__ v) {
    int b = blockIdx.y, blk = blockIdx.x, t = threadIdx.x;
    size_t base = (size_t)b * PER_B + (size_t)blk * 2048 + t;
    const float* qs[KK + 1];
    float cf[KK + 1];
    #pragma unroll
    for (int j = 0; j <= KK; j++) { qs[j] = (j == 0) ? v : g_Q[j - 1]; cf[j] = g_hcoef[j][b]; }
    float* __restrict__ qn = g_Q[KK];
    float nacc = 0.f;
    #pragma unroll
    for (int e = 0; e < 8; e++) {
        size_t idx = base + e * 256;
        float x = g_w[idx];
        #pragma unroll
        for (int j = 0; j <= KK; j++) x -= cf[j] * qs[j][idx];
        qn[idx] = x;
        nacc += x * x;
    }
    float r = blockReduce256(nacc);
    if (t == 0) g_npart[b][blk] = r;
}

__global__ void k_norm_fin(int k) {
    int b = blockIdx.x, t = threadIdx.x;
    float s = g_npart[b][t] + g_npart[b][t + 256];
    float r = blockReduce256(s);
    if (t == 0) {
        float hn = sqrtf(r);
        g_H[b][k + 1][k] = hn;
        g_inv[k + 1][b]  = 1.f / (hn + EPSF);
    }
}

// ---------------- expm of 9x9 (scaling-squaring + Taylor, fp64) ----------------
__global__ void k_expm() {
    const int b = blockIdx.x;
    const int t = threadIdx.x;
    __shared__ double A[81], M[81], P[81], Pn[81];
    __shared__ int ssc;

    if (t < 81) {
        int i = t / 9, j = t % 9;
        double e = 0.0;
        if (i < 8 && j < 8) e = (double)g_H[b][i][j];
        if (i == 0 && j == 8) e = 1.0;
        A[t] = e;
    }
    __syncthreads();
    if (t == 0) {
        double nrm = 0.0;
        for (int i = 0; i < 9; i++) {
            double rs = 0.0;
            for (int j = 0; j < 9; j++) rs += fabs(A[i * 9 + j]);
            if (rs > nrm) nrm = rs;
        }
        int s = 0;
        while (nrm > 0.5 && s < 60) { nrm *= 0.5; s++; }
        ssc = s;
    }
    __syncthreads();
    const int s = ssc;
    if (t < 81) {
        A[t] = ldexp(A[t], -s);
        M[t] = ((t % 10 == 0) ? 1.0 : 0.0) + A[t];
        P[t] = A[t];
    }
    __syncthreads();
    for (int it = 2; it <= 22; it++) {
        if (t < 81) {
            int i = t / 9, j = t % 9;
            double acc = 0.0;
            #pragma unroll
            for (int kk = 0; kk < 9; kk++) acc += P[i * 9 + kk] * A[kk * 9 + j];
            Pn[t] = acc / (double)it;
        }
        __syncthreads();
        if (t < 81) { P[t] = Pn[t]; M[t] += P[t]; }
        __syncthreads();
    }
    for (int q = 0; q < s; q++) {
        if (t < 81) {
            int i = t / 9, j = t % 9;
            double acc = 0.0;
            #pragma unroll
            for (int kk = 0; kk < 9; kk++) acc += M[i * 9 + kk] * M[kk * 9 + j];
            Pn[t] = acc;
        }
        __syncthreads();
        if (t < 81) M[t] = Pn[t];
        __syncthreads();
    }
    if (t < 8) {
        double coord = M[t * 9 + 8];
        g_cf[b][t] = (float)(coord * (double)g_vnorm[b] * (double)g_inv[t][b]);
    }
}

// ---------------- final combine ----------------
__global__ void __launch_bounds__(256) k_combine(const float* __restrict__ v,
                                                 float* __restrict__ out) {
    int b = blockIdx.y, blk = blockIdx.x, t = threadIdx.x;
    size_t base = (size_t)b * PER_B + (size_t)blk * 2048 + t;
    const float* qs[8];
    float cf[8];
    #pragma unroll
    for (int j = 0; j < 8; j++) { qs[j] = (j == 0) ? v : g_Q[j - 1]; cf[j] = g_cf[b][j]; }
    #pragma unroll
    for (int e = 0; e < 8; e++) {
        size_t idx = base + e * 256;
        float x = 0.f;
        #pragma unroll
        for (int j = 0; j < 8; j++) x += cf[j] * qs[j][idx];
        out[idx] = x;
    }
}

// ---------------- driver ----------------
extern "C" void kernel_launch(void* const* d_in, const int* in_sizes, int n_in,
                              void* d_out, int out_size) {
    const float* s0 = (const float*)d_in[0];
    const float* v  = (const float*)d_in[1];
    const float* Wm = (const float*)d_in[2];
    float* out = (float*)d_out;

    const int GEMM_SMEM = 65536;
    cudaFuncSetAttribute(k_gemm_mma, cudaFuncAttributeMaxDynamicSharedMemorySize, GEMM_SMEM);

    dim3 gEl(512, Bb);
    dim3 gRep(HW / 32, Bb);
    dim3 gGemm(HW / 128, 2, Bb);   // 32 p-tiles x 2 m-tiles x 8 batches

    k_splitW<<<Cc * Cc / 256, 256>>>(Wm);
    k_selfdot<<<gEl, 256>>>(v);
    k_vnorm_fin<<<Bb, 256>>>();

    for (int k = 0; k < 8; k++) {
        k_replicator<<<gRep, 256>>>(s0, v, k);
        k_gemm_mma<<<gGemm, 256, GEMM_SMEM>>>();

        switch (k) {
            case 0: k_dots<0><<<gEl, 256>>>(v); break;
            case 1: k_dots<1><<<gEl, 256>>>(v); break;
            case 2: k_dots<2><<<gEl, 256>>>(v); break;
            case 3: k_dots<3><<<gEl, 256>>>(v); break;
            case 4: k_dots<4><<<gEl, 256>>>(v); break;
            case 5: k_dots<5><<<gEl, 256>>>(v); break;
            case 6: k_dots<6><<<gEl, 256>>>(v); break;
            case 7: k_dots<7><<<gEl, 256>>>(v); break;
        }
        k_dots_fin<<<dim3(k + 1, Bb), 256>>>(k);

        if (k < 7) {
            switch (k) {
                case 0: k_update<0><<<gEl, 256>>>(v); break;
                case 1: k_update<1><<<gEl, 256>>>(v); break;
                case 2: k_update<2><<<gEl, 256>>>(v); break;
                case 3: k_update<3><<<gEl, 256>>>(v); break;
                case 4: k_update<4><<<gEl, 256>>>(v); break;
                case 5: k_update<5><<<gEl, 256>>>(v); break;
                case 6: k_update<6><<<gEl, 256>>>(v); break;
            }
            k_norm_fin<<<Bb, 256>>>(k);
        }
    }

    k_expm<<<Bb, 128>>>();
    k_combine<<<gEl, 256>>>(v, out);
}